// round 7
// baseline (speedup 1.0000x reference)
#include <cuda_runtime.h>
#include <cstdint>

#define THREADS 896      // 28 warps
#define EPT 2            // 1792 elements per block
#define SMEM_BYTES 204800  // 3*64KB cores + 8KB table

__device__ float g_scratch[2097152];   // 262144 * 8 floats (8MB)

// Stage one middle core (8 x 256 x 8 floats = 4096 float4 chunks).
// Global float4 g = r*512 + u (u = idx*2 + half); shared float4 s = idx*16 + half*8 + r.
// Slice contiguous 256B, chunk bank-group = r -> conflict-free rotated reads.
__device__ __forceinline__ void stage_mid(float* dst, const float* __restrict__ src, int tid)
{
    const int lane = tid & 31;
    const int wrp  = tid >> 5;          // 0..27
    const int r    = lane >> 2;
    const int m    = lane & 3;
    const char* gbase = (const char*)src;
    unsigned sbase = (unsigned)__cvta_generic_to_shared(dst);
    const int ub = wrp * 4 + m;         // 0..111
#pragma unroll
    for (int t = 0; t < 5; t++) {
        int u = ub + t * 112;
        if (u < 512) {
            long goff = ((long)(r * 512 + u)) << 4;
            unsigned soff = (unsigned)((((u >> 1) << 4) + ((u & 1) << 3) + r) << 4);
            asm volatile("cp.async.cg.shared.global [%0], [%1], 16;\n"
                         :: "r"(sbase + soff), "l"(gbase + goff) : "memory");
        }
    }
    asm volatile("cp.async.commit_group;\n" ::: "memory");
}

// One 8x8 matvec: w (rotated) x slice at byte offset so in slab -> w (rotated).
__device__ __forceinline__ void matvec(float w[8], const float* slab, int so,
                                       const int roff[8], bool r1, bool r2, bool r4)
{
    const char* p = (const char*)slab + so;
    float nv[8];
    {
        float4 m[8];
#pragma unroll
        for (int c = 0; c < 8; c++) m[c] = *(const float4*)(p + roff[c]);
        nv[0] = w[0] * m[0].x; nv[1] = w[0] * m[0].y;
        nv[2] = w[0] * m[0].z; nv[3] = w[0] * m[0].w;
#pragma unroll
        for (int c = 1; c < 8; c++) {
            const float wc = w[c];
            nv[0] = fmaf(wc, m[c].x, nv[0]);
            nv[1] = fmaf(wc, m[c].y, nv[1]);
            nv[2] = fmaf(wc, m[c].z, nv[2]);
            nv[3] = fmaf(wc, m[c].w, nv[3]);
        }
    }
    {
        float4 m[8];
#pragma unroll
        for (int c = 0; c < 8; c++) m[c] = *(const float4*)(p + 128 + roff[c]);
        nv[4] = w[0] * m[0].x; nv[5] = w[0] * m[0].y;
        nv[6] = w[0] * m[0].z; nv[7] = w[0] * m[0].w;
#pragma unroll
        for (int c = 1; c < 8; c++) {
            const float wc = w[c];
            nv[4] = fmaf(wc, m[c].x, nv[4]);
            nv[5] = fmaf(wc, m[c].y, nv[5]);
            nv[6] = fmaf(wc, m[c].z, nv[6]);
            nv[7] = fmaf(wc, m[c].w, nv[7]);
        }
    }
    float a[8], b[8];
#pragma unroll
    for (int j = 0; j < 8; j++) a[j] = r1 ? nv[(j + 1) & 7] : nv[j];
#pragma unroll
    for (int j = 0; j < 8; j++) b[j] = r2 ? a[(j + 2) & 7] : a[j];
#pragma unroll
    for (int j = 0; j < 8; j++) w[j] = r4 ? b[(j + 4) & 7] : b[j];
}

// ---------------- Kernel A: stages 1-3, vec -> scratch ----------------
__global__ void __launch_bounds__(THREADS, 1)
tt_passA(const float* __restrict__ G0, const float* __restrict__ G1,
         const float* __restrict__ G2, const float* __restrict__ G3,
         const int* __restrict__ states, int Btot)
{
    extern __shared__ float smem[];
    float* bufs0 = smem;
    float* bufs1 = smem + 16384;
    float* bufs2 = smem + 32768;
    float* g0s   = smem + 49152;

    const int tid = threadIdx.x;
    const int rho = tid & 7;

    stage_mid(bufs0, G1, tid);
    stage_mid(bufs1, G2, tid);
    stage_mid(bufs2, G3, tid);

    // G0 table (512 float4, already [idx][r]).
#pragma unroll
    for (int i = tid; i < 512; i += THREADS)
        ((float4*)g0s)[i] = ((const float4*)G0)[i];

    int roff[8];
#pragma unroll
    for (int c = 0; c < 8; c++) roff[c] = ((c + rho) & 7) << 4;
    const bool r1 = (rho & 1) != 0, r2 = (rho & 2) != 0, r4 = (rho & 4) != 0;

    const int base = blockIdx.x * (THREADS * EPT) + tid;
    unsigned actmask = 0;
    int s1[EPT], s2[EPT], s3[EPT];
    float w[EPT][8];

    // Load indices + init w (behind buf0/g0s readiness).
    int g0off[EPT];
#pragma unroll
    for (int i = 0; i < EPT; i++) {
        int e = base + i * THREADS;
        bool act = (e < Btot);
        int ec = act ? e : 0;
        if (act) actmask |= (1u << i);
        const int* sp = states + ec * 7;
        g0off[i] = __ldg(sp);
        s1[i] = __ldg(sp + 1) << 8;
        s2[i] = __ldg(sp + 2) << 8;
        s3[i] = __ldg(sp + 3) << 8;
    }

    asm volatile("cp.async.wait_group 2;\n" ::: "memory");
    __syncthreads();                              // buf0 + g0s visible

#pragma unroll
    for (int i = 0; i < EPT; i++) {
        const char* p0 = (const char*)(g0s) + g0off[i] * 32;
#pragma unroll
        for (int j = 0; j < 8; j++) w[i][j] = *(const float*)(p0 + (roff[j] >> 2));
        matvec(w[i], bufs0, s1[i], roff, r1, r2, r4);   // stage 1
    }

    asm volatile("cp.async.wait_group 0;\n" ::: "memory");
    __syncthreads();                              // buf1, buf2 visible

#pragma unroll
    for (int i = 0; i < EPT; i++) {
        matvec(w[i], bufs1, s2[i], roff, r1, r2, r4);   // stage 2
        matvec(w[i], bufs2, s3[i], roff, r1, r2, r4);   // stage 3
        if (actmask & (1u << i)) {
            int e = base + i * THREADS;
            float4* dst = (float4*)(g_scratch + (size_t)e * 8);
            dst[0] = make_float4(w[i][0], w[i][1], w[i][2], w[i][3]);
            dst[1] = make_float4(w[i][4], w[i][5], w[i][6], w[i][7]);
        }
    }
}

// ---------------- Kernel B: stages 4-6 + G7 dot -> out ----------------
__global__ void __launch_bounds__(THREADS, 1)
tt_passB(const float* __restrict__ G4, const float* __restrict__ G5,
         const float* __restrict__ G6, const float* __restrict__ G7,
         const int* __restrict__ states, const int* __restrict__ actions,
         float* __restrict__ out, int Btot)
{
    extern __shared__ float smem[];
    float* bufs0 = smem;
    float* bufs1 = smem + 16384;
    float* bufs2 = smem + 32768;
    float* g7s   = smem + 49152;

    const int tid = threadIdx.x;
    const int rho = tid & 7;

    stage_mid(bufs0, G4, tid);
    stage_mid(bufs1, G5, tid);
    stage_mid(bufs2, G6, tid);

    // G7 transposed table: global [r][idx] -> smem [idx][r].
#pragma unroll
    for (int i = tid; i < 2048; i += THREADS) {
        int idx = i & 255, r = i >> 8;
        g7s[idx * 8 + r] = G7[r * 256 + idx];
    }

    int roff[8];
#pragma unroll
    for (int c = 0; c < 8; c++) roff[c] = ((c + rho) & 7) << 4;
    const bool r1 = (rho & 1) != 0, r2 = (rho & 2) != 0, r4 = (rho & 4) != 0;

    const int base = blockIdx.x * (THREADS * EPT) + tid;
    unsigned actmask = 0;
    int s4[EPT], s5[EPT], s6[EPT], g7off[EPT];
    float w[EPT][8];

#pragma unroll
    for (int i = 0; i < EPT; i++) {
        int e = base + i * THREADS;
        bool act = (e < Btot);
        int ec = act ? e : 0;
        if (act) actmask |= (1u << i);
        const int* sp = states + ec * 7;
        s4[i] = __ldg(sp + 4) << 8;
        s5[i] = __ldg(sp + 5) << 8;
        s6[i] = __ldg(sp + 6) << 8;
        g7off[i] = __ldg(actions + ec);
        const float4* src = (const float4*)(g_scratch + (size_t)ec * 8);
        float4 lo = src[0], hi = src[1];
        w[i][0] = lo.x; w[i][1] = lo.y; w[i][2] = lo.z; w[i][3] = lo.w;
        w[i][4] = hi.x; w[i][5] = hi.y; w[i][6] = hi.z; w[i][7] = hi.w;
    }

    asm volatile("cp.async.wait_group 2;\n" ::: "memory");
    __syncthreads();                              // buf0 + g7s visible

#pragma unroll
    for (int i = 0; i < EPT; i++)
        matvec(w[i], bufs0, s4[i], roff, r1, r2, r4);   // stage 4

    asm volatile("cp.async.wait_group 0;\n" ::: "memory");
    __syncthreads();                              // buf1, buf2 visible

#pragma unroll
    for (int i = 0; i < EPT; i++) {
        matvec(w[i], bufs1, s5[i], roff, r1, r2, r4);   // stage 5
        matvec(w[i], bufs2, s6[i], roff, r1, r2, r4);   // stage 6
        const char* p7 = (const char*)(g7s) + g7off[i] * 32;
        float acc = 0.f;
#pragma unroll
        for (int c = 0; c < 8; c++)
            acc = fmaf(w[i][c], *(const float*)(p7 + (roff[c] >> 2)), acc);
        if (actmask & (1u << i)) out[base + i * THREADS] = acc;
    }
}

extern "C" void kernel_launch(void* const* d_in, const int* in_sizes, int n_in,
                              void* d_out, int out_size)
{
    const float* G0 = (const float*)d_in[0];
    const float* G1 = (const float*)d_in[1];
    const float* G2 = (const float*)d_in[2];
    const float* G3 = (const float*)d_in[3];
    const float* G4 = (const float*)d_in[4];
    const float* G5 = (const float*)d_in[5];
    const float* G6 = (const float*)d_in[6];
    const float* G7 = (const float*)d_in[7];
    const int* states  = (const int*)d_in[8];
    const int* actions = (const int*)d_in[9];
    const int B = in_sizes[9];

    cudaFuncSetAttribute(tt_passA, cudaFuncAttributeMaxDynamicSharedMemorySize, SMEM_BYTES);
    cudaFuncSetAttribute(tt_passB, cudaFuncAttributeMaxDynamicSharedMemorySize, SMEM_BYTES);

    const int per_block = THREADS * EPT;
    const int grid = (B + per_block - 1) / per_block;

    tt_passA<<<grid, THREADS, SMEM_BYTES>>>(G0, G1, G2, G3, states, B);
    tt_passB<<<grid, THREADS, SMEM_BYTES>>>(G4, G5, G6, G7, states, actions,
                                            (float*)d_out, B);
}

// round 9
// speedup vs baseline: 1.1105x; 1.1105x over previous
#include <cuda_runtime.h>
#include <cstdint>

#define THREADS 448     // 14 warps
#define EPT 4           // 1792 elements per block -> grid 147
#define SMEM_BYTES 212992

// Stage one middle core (8 x 256 x 8 floats = 4096 float4 chunks).
// Global float4 index g = r*512 + u   (u = idx*2 + half)
// Shared float4 index s = idx*16 + half*8 + r  (slice contiguous, chunk bank-group = r)
// Lane mapping: r = lane>>2 (8 groups x 4 lanes), 4 consecutive lanes read 64B global.
__device__ __forceinline__ void stage_mid(float* dst, const float* __restrict__ src, int tid)
{
    const int lane = tid & 31;
    const int wrp  = tid >> 5;          // 0..13
    const int r    = lane >> 2;
    const int m    = lane & 3;
    const char* gbase = (const char*)src;
    unsigned sbase = (unsigned)__cvta_generic_to_shared(dst);
    const int ub = wrp * 4 + m;         // 0..55
#pragma unroll
    for (int t = 0; t < 10; t++) {
        int u = ub + t * 56;
        if (u < 512) {
            long goff = ((long)(r * 512 + u)) << 4;
            unsigned soff = (unsigned)((((u >> 1) << 4) + ((u & 1) << 3) + r) << 4);
            asm volatile("cp.async.cg.shared.global [%0], [%1], 16;\n"
                         :: "r"(sbase + soff), "l"(gbase + goff) : "memory");
        }
    }
    asm volatile("cp.async.commit_group;\n" ::: "memory");
}

__global__ void __launch_bounds__(THREADS, 1)
tt_gather_kernel(const float* __restrict__ G0, const float* __restrict__ G1,
                 const float* __restrict__ G2, const float* __restrict__ G3,
                 const float* __restrict__ G4, const float* __restrict__ G5,
                 const float* __restrict__ G6, const float* __restrict__ G7,
                 const int* __restrict__ states, const int* __restrict__ actions,
                 float* __restrict__ out, int Btot)
{
    extern __shared__ float smem[];
    float* bufs[3] = { smem, smem + 16384, smem + 32768 };
    float* g0s = smem + 49152;
    float* g7s = smem + 51200;

    const int tid = threadIdx.x;
    const int lane = tid & 31;
    // Rotation offset: distinct within each lane-quarter AND within each
    // component-conflict set {l, l+8, l+16, l+24} -> conflict-free LDS.128
    // under both possible wavefront-splitting models.
    const int rho = (lane + (lane >> 3)) & 7;

    // Prologue: stage G1, G2, G3 (3 commit groups -> depth-2 pipeline).
    stage_mid(bufs[0], G1, tid);
    stage_mid(bufs[1], G2, tid);
    stage_mid(bufs[2], G3, tid);

    // Stage G0 (512 float4, already [idx][r]).
#pragma unroll
    for (int i = tid; i < 512; i += THREADS)
        ((float4*)g0s)[i] = ((const float4*)G0)[i];

    // Stage G7 transposed: global [r][idx] -> smem [idx][r].
#pragma unroll
    for (int i = tid; i < 2048; i += THREADS) {
        int idx = i & 255, r = i >> 8;
        g7s[idx * 8 + r] = G7[r * 256 + idx];
    }

    // Per-thread rotated chunk byte offsets.
    int roff[8];
#pragma unroll
    for (int c = 0; c < 8; c++) roff[c] = ((c + rho) & 7) << 4;

    // Load indices for my EPT elements.
    const int base = blockIdx.x * (THREADS * EPT) + tid;
    unsigned actmask = 0;
    int g0off[EPT], g7off[EPT], soff[EPT][6];
#pragma unroll
    for (int i = 0; i < EPT; i++) {
        int e = base + i * THREADS;
        bool act = (e < Btot);
        int ec = act ? e : 0;
        if (act) actmask |= (1u << i);
        const int* sp = states + ec * 7;
        g0off[i] = __ldg(sp);
#pragma unroll
        for (int k = 0; k < 6; k++) soff[i][k] = __ldg(sp + k + 1) << 8;  // idx*256 bytes
        g7off[i] = __ldg(actions + ec);
    }

    __syncthreads();   // g0s/g7s visible

    // Init rotated vec from G0: w[j] = vec0[(j+rho)&7]
    float w[EPT][8];
#pragma unroll
    for (int i = 0; i < EPT; i++) {
        const char* p0 = (const char*)(g0s) + g0off[i] * 32;
#pragma unroll
        for (int j = 0; j < 8; j++) w[i][j] = *(const float*)(p0 + (roff[j] >> 2));
    }

    const bool r1 = (rho & 1) != 0, r2 = (rho & 2) != 0, r4 = (rho & 4) != 0;
    const float* nextG[3] = { G4, G5, G6 };

#pragma unroll
    for (int k = 1; k <= 6; k++) {
        // Wait for stage-k buffer; allow 2 younger groups in flight.
        if (k <= 4) asm volatile("cp.async.wait_group 2;\n" ::: "memory");
        else if (k == 5) asm volatile("cp.async.wait_group 1;\n" ::: "memory");
        else asm volatile("cp.async.wait_group 0;\n" ::: "memory");
        __syncthreads();

        const float* cur = bufs[(k - 1) % 3];

#pragma unroll
        for (int i = 0; i < EPT; i++) {
            const char* p = (const char*)cur + soff[i][k - 1];
            // Batch all 16 chunk loads first (MLP), then FMA.
            float4 m[16];
#pragma unroll
            for (int c = 0; c < 8; c++) {
                m[c]     = *(const float4*)(p + roff[c]);
                m[c + 8] = *(const float4*)(p + 128 + roff[c]);
            }
            float nv[8];
#pragma unroll
            for (int s = 0; s < 8; s++) nv[s] = 0.f;
#pragma unroll
            for (int c = 0; c < 8; c++) {
                const float wc = w[i][c];
                nv[0] = fmaf(wc, m[c].x, nv[0]);
                nv[1] = fmaf(wc, m[c].y, nv[1]);
                nv[2] = fmaf(wc, m[c].z, nv[2]);
                nv[3] = fmaf(wc, m[c].w, nv[3]);
                nv[4] = fmaf(wc, m[c + 8].x, nv[4]);
                nv[5] = fmaf(wc, m[c + 8].y, nv[5]);
                nv[6] = fmaf(wc, m[c + 8].z, nv[6]);
                nv[7] = fmaf(wc, m[c + 8].w, nv[7]);
            }
            // Barrel-rotate nv left by rho into w[i] (predicated selects).
            float a[8], b[8];
#pragma unroll
            for (int j = 0; j < 8; j++) a[j] = r1 ? nv[(j + 1) & 7] : nv[j];
#pragma unroll
            for (int j = 0; j < 8; j++) b[j] = r2 ? a[(j + 2) & 7] : a[j];
#pragma unroll
            for (int j = 0; j < 8; j++) w[i][j] = r4 ? b[(j + 4) & 7] : b[j];
        }

        // Refill this buffer with core k+3 after all warps finished reading it.
        if (k <= 3) {
            __syncthreads();
            stage_mid(bufs[(k - 1) % 3], nextG[k - 1], tid);
        }
    }

    // Final: dot with G7 slice and store.
#pragma unroll
    for (int i = 0; i < EPT; i++) {
        const char* p7 = (const char*)(g7s) + g7off[i] * 32;
        float acc = 0.f;
#pragma unroll
        for (int c = 0; c < 8; c++)
            acc = fmaf(w[i][c], *(const float*)(p7 + (roff[c] >> 2)), acc);
        if (actmask & (1u << i)) out[base + i * THREADS] = acc;
    }
}

extern "C" void kernel_launch(void* const* d_in, const int* in_sizes, int n_in,
                              void* d_out, int out_size)
{
    const float* G0 = (const float*)d_in[0];
    const float* G1 = (const float*)d_in[1];
    const float* G2 = (const float*)d_in[2];
    const float* G3 = (const float*)d_in[3];
    const float* G4 = (const float*)d_in[4];
    const float* G5 = (const float*)d_in[5];
    const float* G6 = (const float*)d_in[6];
    const float* G7 = (const float*)d_in[7];
    const int* states  = (const int*)d_in[8];
    const int* actions = (const int*)d_in[9];
    const int B = in_sizes[9];

    cudaFuncSetAttribute(tt_gather_kernel,
                         cudaFuncAttributeMaxDynamicSharedMemorySize, SMEM_BYTES);

    const int per_block = THREADS * EPT;
    const int grid = (B + per_block - 1) / per_block;
    tt_gather_kernel<<<grid, THREADS, SMEM_BYTES>>>(
        G0, G1, G2, G3, G4, G5, G6, G7, states, actions, (float*)d_out, B);
}